// round 2
// baseline (speedup 1.0000x reference)
#include <cuda_runtime.h>
#include <math.h>
#include <stdint.h>

#define SEQ   1024
#define BATCH 4
#define DM    1024
#define NH    16
#define DKH   64
#define DFF   4096
#define ROWS  (BATCH*SEQ)       // 4096
#define LN_EPS 1e-6f
#define NEGINF -1e9f

// ---------------- scratch (device globals; no allocation) ----------------
__device__ float g_xn[ROWS*DM];                       // 16 MB
__device__ float g_q [ROWS*DM];
__device__ float g_k [ROWS*DM];
__device__ float g_v [ROWS*DM];
__device__ float g_sc[(size_t)BATCH*NH*SEQ*SEQ];      // 256 MB
__device__ float g_at[ROWS*DM];
__device__ float g_x1[ROWS*DM];
__device__ float g_ff[(size_t)ROWS*DFF];              // 64 MB

// ---------------- block reductions (256 threads) ----------------
__device__ __forceinline__ float block_sum256(float v, float* red) {
    #pragma unroll
    for (int o = 16; o > 0; o >>= 1) v += __shfl_xor_sync(0xffffffffu, v, o);
    if ((threadIdx.x & 31) == 0) red[threadIdx.x >> 5] = v;
    __syncthreads();
    float t = 0.f;
    #pragma unroll
    for (int i = 0; i < 8; i++) t += red[i];
    __syncthreads();
    return t;
}

__device__ __forceinline__ float block_max256(float v, float* red) {
    #pragma unroll
    for (int o = 16; o > 0; o >>= 1) v = fmaxf(v, __shfl_xor_sync(0xffffffffu, v, o));
    if ((threadIdx.x & 31) == 0) red[threadIdx.x >> 5] = v;
    __syncthreads();
    float t = -INFINITY;
    #pragma unroll
    for (int i = 0; i < 8; i++) t = fmaxf(t, red[i]);
    __syncthreads();
    return t;
}

// ---------------- layernorm (scalar alpha/beta, ddof=1, eps on std) -------
__global__ void ln_kernel(const float* __restrict__ x, float* __restrict__ y,
                          const float* __restrict__ alpha, const float* __restrict__ beta) {
    __shared__ float red[8];
    const int row = blockIdx.x;
    const float* xr = x + (size_t)row * DM;
    float*       yr = y + (size_t)row * DM;

    float v[4];
    float s = 0.f;
    #pragma unroll
    for (int i = 0; i < 4; i++) { v[i] = xr[threadIdx.x + i*256]; s += v[i]; }
    const float mean = block_sum256(s, red) * (1.f / DM);

    float d2 = 0.f;
    #pragma unroll
    for (int i = 0; i < 4; i++) { float d = v[i] - mean; d2 += d * d; }
    const float var = block_sum256(d2, red) * (1.f / (DM - 1));   // Bessel
    const float inv = alpha[0] / (sqrtf(var) + LN_EPS);
    const float b0  = beta[0];
    #pragma unroll
    for (int i = 0; i < 4; i++)
        yr[threadIdx.x + i*256] = (v[i] - mean) * inv + b0;
}

// ---------------- generic fp32 GEMM: C = A[M,K] @ B[K,N] + bias ----------
// 64x64 tile, BK=16, 256 threads, 4x4 per thread
template<bool RELU, bool RES>
__global__ void gemm_kernel(const float* __restrict__ A, const float* __restrict__ B,
                            const float* __restrict__ bias, const float* __restrict__ res,
                            float* __restrict__ C, int M, int N, int K) {
    __shared__ float As[16][64];   // transposed: As[k][m]
    __shared__ float Bs[16][64];

    const int bm = blockIdx.y * 64;
    const int bn = blockIdx.x * 64;
    const int tid = threadIdx.x;
    const int ty = tid >> 4, tx = tid & 15;
    const int arow = tid >> 2, ac = (tid & 3) << 2;
    const int brow = tid >> 4, bc = (tid & 15) << 2;

    float acc[4][4] = {};

    for (int k0 = 0; k0 < K; k0 += 16) {
        float4 a4 = *(const float4*)&A[(size_t)(bm + arow) * K + k0 + ac];
        As[ac+0][arow] = a4.x; As[ac+1][arow] = a4.y;
        As[ac+2][arow] = a4.z; As[ac+3][arow] = a4.w;
        *(float4*)&Bs[brow][bc] =
            *(const float4*)&B[(size_t)(k0 + brow) * N + bn + bc];
        __syncthreads();

        #pragma unroll
        for (int k = 0; k < 16; k++) {
            float4 a = *(const float4*)&As[k][ty << 2];
            float4 b = *(const float4*)&Bs[k][tx << 2];
            float av[4] = {a.x, a.y, a.z, a.w};
            float bv[4] = {b.x, b.y, b.z, b.w};
            #pragma unroll
            for (int i = 0; i < 4; i++)
                #pragma unroll
                for (int j = 0; j < 4; j++)
                    acc[i][j] = fmaf(av[i], bv[j], acc[i][j]);
        }
        __syncthreads();
    }

    #pragma unroll
    for (int i = 0; i < 4; i++) {
        const int m = bm + (ty << 2) + i;
        #pragma unroll
        for (int j = 0; j < 4; j++) {
            const int n = bn + (tx << 2) + j;
            float c = acc[i][j] + bias[n];
            if (RELU) c = fmaxf(c, 0.f);
            if (RES)  c += res[(size_t)m * N + n];
            C[(size_t)m * N + n] = c;
        }
    }
}

// ---------------- attention scores: S[bh,q,k] = (Q·K)/8, masked ----------
// grid: (k-tile 16, q-tile 16, bh 64), 256 threads, 4x4 per thread, Kdim=64
__global__ void scores_kernel(const float* __restrict__ Q, const float* __restrict__ Km,
                              const int* __restrict__ mask, float* __restrict__ S) {
    __shared__ float Qs[64][65];
    __shared__ float Ks[64][65];

    const int bh = blockIdx.z, b = bh >> 4, h = bh & 15;
    const int q0 = blockIdx.y * 64, k0 = blockIdx.x * 64;
    const int tid = threadIdx.x;

    #pragma unroll
    for (int p = 0; p < 4; p++) {
        int idx = tid + p * 256;
        int row = idx >> 4;             // 0..63
        int c4  = (idx & 15) << 2;      // 0..60
        float4 a = *(const float4*)&Q [((size_t)(b*SEQ + q0 + row)) * DM + h*DKH + c4];
        Qs[row][c4+0] = a.x; Qs[row][c4+1] = a.y; Qs[row][c4+2] = a.z; Qs[row][c4+3] = a.w;
        float4 kk = *(const float4*)&Km[((size_t)(b*SEQ + k0 + row)) * DM + h*DKH + c4];
        Ks[row][c4+0] = kk.x; Ks[row][c4+1] = kk.y; Ks[row][c4+2] = kk.z; Ks[row][c4+3] = kk.w;
    }
    __syncthreads();

    const int ty = tid >> 4, tx = tid & 15;
    float acc[4][4] = {};
    #pragma unroll 16
    for (int d = 0; d < 64; d++) {
        float av[4], bv[4];
        #pragma unroll
        for (int i = 0; i < 4; i++) av[i] = Qs[(ty << 2) + i][d];
        #pragma unroll
        for (int j = 0; j < 4; j++) bv[j] = Ks[(tx << 2) + j][d];
        #pragma unroll
        for (int i = 0; i < 4; i++)
            #pragma unroll
            for (int j = 0; j < 4; j++)
                acc[i][j] = fmaf(av[i], bv[j], acc[i][j]);
    }

    const float scale = 0.125f;   // 1/sqrt(64)
    #pragma unroll
    for (int i = 0; i < 4; i++) {
        const int qi = q0 + (ty << 2) + i;
        #pragma unroll
        for (int j = 0; j < 4; j++) {
            const int ki = k0 + (tx << 2) + j;
            float sv = acc[i][j] * scale;
            if (mask[b * SEQ + ki] == 0) sv = NEGINF;
            S[((size_t)bh * SEQ + qi) * SEQ + ki] = sv;
        }
    }
}

// ---------------- softmax along last dim (rows of length 1024) -----------
__global__ void softmax_kernel(float* __restrict__ S) {
    __shared__ float red[8];
    float* p = S + (size_t)blockIdx.x * SEQ;
    float v[4];
    float m = -INFINITY;
    #pragma unroll
    for (int i = 0; i < 4; i++) { v[i] = p[threadIdx.x + i*256]; m = fmaxf(m, v[i]); }
    m = block_max256(m, red);
    float s = 0.f;
    #pragma unroll
    for (int i = 0; i < 4; i++) { v[i] = expf(v[i] - m); s += v[i]; }
    s = block_sum256(s, red);
    const float inv = 1.f / s;
    #pragma unroll
    for (int i = 0; i < 4; i++) p[threadIdx.x + i*256] = v[i] * inv;
}

// ---------------- attn @ V : O[b,s,h*64+d] = sum_k P[bh,s,k] V[b,k,h*64+d]
// grid: (m-tile 16, bh 64), 256 threads, 4x4 per thread, BK=32
__global__ void attnv_kernel(const float* __restrict__ P, const float* __restrict__ V,
                             float* __restrict__ O) {
    __shared__ float Ps[64][33];
    __shared__ float Vs[32][65];

    const int bh = blockIdx.y, b = bh >> 4, h = bh & 15;
    const int m0 = blockIdx.x * 64;
    const int tid = threadIdx.x;
    const float* Pbh = P + (size_t)bh * SEQ * SEQ;

    float acc[4][4] = {};

    for (int k0 = 0; k0 < SEQ; k0 += 32) {
        #pragma unroll
        for (int p = 0; p < 2; p++) {
            int idx = tid + p * 256;
            int row = idx >> 3;            // 0..63
            int c4  = (idx & 7) << 2;      // 0..28
            float4 a = *(const float4*)&Pbh[(size_t)(m0 + row) * SEQ + k0 + c4];
            Ps[row][c4+0] = a.x; Ps[row][c4+1] = a.y; Ps[row][c4+2] = a.z; Ps[row][c4+3] = a.w;
        }
        #pragma unroll
        for (int p = 0; p < 2; p++) {
            int idx = tid + p * 256;
            int row = idx >> 4;            // 0..31
            int c4  = (idx & 15) << 2;     // 0..60
            float4 vv = *(const float4*)&V[(size_t)(b*SEQ + k0 + row) * DM + h*DKH + c4];
            Vs[row][c4+0] = vv.x; Vs[row][c4+1] = vv.y; Vs[row][c4+2] = vv.z; Vs[row][c4+3] = vv.w;
        }
        __syncthreads();

        const int ty = tid >> 4, tx = tid & 15;
        #pragma unroll 8
        for (int k = 0; k < 32; k++) {
            float av[4], bv[4];
            #pragma unroll
            for (int i = 0; i < 4; i++) av[i] = Ps[(ty << 2) + i][k];
            #pragma unroll
            for (int j = 0; j < 4; j++) bv[j] = Vs[k][(tx << 2) + j];
            #pragma unroll
            for (int i = 0; i < 4; i++)
                #pragma unroll
                for (int j = 0; j < 4; j++)
                    acc[i][j] = fmaf(av[i], bv[j], acc[i][j]);
        }
        __syncthreads();
    }

    const int ty = tid >> 4, tx = tid & 15;
    #pragma unroll
    for (int i = 0; i < 4; i++)
        #pragma unroll
        for (int j = 0; j < 4; j++)
            O[(size_t)(b*SEQ + m0 + (ty << 2) + i) * DM + h*DKH + (tx << 2) + j] = acc[i][j];
}

// ---------------- launch ----------------
extern "C" void kernel_launch(void* const* d_in, const int* in_sizes, int n_in,
                              void* d_out, int out_size) {
    const float* x   = (const float*)d_in[0];
    const int*   mask= (const int*)  d_in[1];
    const float* Wq  = (const float*)d_in[2];
    const float* bq  = (const float*)d_in[3];
    const float* Wk  = (const float*)d_in[4];
    const float* bk  = (const float*)d_in[5];
    const float* Wv  = (const float*)d_in[6];
    const float* bv  = (const float*)d_in[7];
    const float* Wo  = (const float*)d_in[8];
    const float* bo  = (const float*)d_in[9];
    const float* W1  = (const float*)d_in[10];
    const float* b1  = (const float*)d_in[11];
    const float* W2  = (const float*)d_in[12];
    const float* b2  = (const float*)d_in[13];
    const float* a1  = (const float*)d_in[14];
    const float* be1 = (const float*)d_in[15];
    const float* a2  = (const float*)d_in[16];
    const float* be2 = (const float*)d_in[17];
    float* out = (float*)d_out;

    float *xn, *q, *k, *v, *sc, *at, *x1, *ff;
    cudaGetSymbolAddress((void**)&xn, g_xn);
    cudaGetSymbolAddress((void**)&q,  g_q);
    cudaGetSymbolAddress((void**)&k,  g_k);
    cudaGetSymbolAddress((void**)&v,  g_v);
    cudaGetSymbolAddress((void**)&sc, g_sc);
    cudaGetSymbolAddress((void**)&at, g_at);
    cudaGetSymbolAddress((void**)&x1, g_x1);
    cudaGetSymbolAddress((void**)&ff, g_ff);

    // 1) LN1
    ln_kernel<<<ROWS, 256>>>(x, xn, a1, be1);
    // 2-4) Q,K,V projections
    gemm_kernel<false,false><<<dim3(DM/64, ROWS/64), 256>>>(xn, Wq, bq, nullptr, q, ROWS, DM, DM);
    gemm_kernel<false,false><<<dim3(DM/64, ROWS/64), 256>>>(xn, Wk, bk, nullptr, k, ROWS, DM, DM);
    gemm_kernel<false,false><<<dim3(DM/64, ROWS/64), 256>>>(xn, Wv, bv, nullptr, v, ROWS, DM, DM);
    // 5) scores (scaled + masked)
    scores_kernel<<<dim3(SEQ/64, SEQ/64, BATCH*NH), 256>>>(q, k, mask, sc);
    // 6) softmax
    softmax_kernel<<<BATCH*NH*SEQ, 256>>>(sc);
    // 7) attn @ V
    attnv_kernel<<<dim3(SEQ/64, BATCH*NH), 256>>>(sc, v, at);
    // 8) output projection + residual (x)
    gemm_kernel<false,true><<<dim3(DM/64, ROWS/64), 256>>>(at, Wo, bo, x, x1, ROWS, DM, DM);
    // 9) LN2
    ln_kernel<<<ROWS, 256>>>(x1, xn, a2, be2);
    // 10) FFN up + relu
    gemm_kernel<true,false><<<dim3(DFF/64, ROWS/64), 256>>>(xn, W1, b1, nullptr, ff, ROWS, DFF, DM);
    // 11) FFN down + residual (x1) -> out
    gemm_kernel<false,true><<<dim3(DM/64, ROWS/64), 256>>>(ff, W2, b2, x1, out, ROWS, DM, DFF);
}

// round 3
// speedup vs baseline: 3.4172x; 3.4172x over previous
#include <cuda_runtime.h>
#include <math.h>
#include <stdint.h>

#define SEQ   1024
#define BATCH 4
#define DM    1024
#define NH    16
#define DKH   64
#define DFF   4096
#define ROWS  (BATCH*SEQ)       // 4096
#define LN_EPS 1e-6f
#define NEGINF -1e9f

// ---------------- scratch (device globals; no allocation) ----------------
__device__ float g_xn[ROWS*DM];
__device__ float g_q [ROWS*DM];
__device__ float g_k [ROWS*DM];
__device__ float g_v [ROWS*DM];
__device__ float g_sc[(size_t)BATCH*NH*SEQ*SEQ];      // 256 MB
__device__ float g_at[ROWS*DM];
__device__ float g_x1[ROWS*DM];
__device__ float g_ff[(size_t)ROWS*DFF];              // 64 MB
__device__ float g_wq[DM*DM];
__device__ float g_wk[DM*DM];
__device__ float g_wv[DM*DM];
__device__ float g_wo[DM*DM];
__device__ float g_w1[DM*DFF];
__device__ float g_w2[DFF*DM];

// ---------------- helpers ----------------
__device__ __forceinline__ float tf32r(float x) {
    unsigned u;
    asm("cvt.rna.tf32.f32 %0, %1;" : "=r"(u) : "f"(x));
    return __uint_as_float(u);
}

__device__ __forceinline__ unsigned su(const void* p) {
    return (unsigned)__cvta_generic_to_shared(p);
}

#define CPA16(dst, src) asm volatile("cp.async.cg.shared.global [%0], [%1], 16;" :: "r"(dst), "l"(src))
#define CPCOMMIT()      asm volatile("cp.async.commit_group;")
#define CPWAIT1()       asm volatile("cp.async.wait_group 1;")
#define CPWAIT0()       asm volatile("cp.async.wait_group 0;")

__device__ __forceinline__ void mma8(float* c, const unsigned* a, const unsigned* b) {
    asm volatile(
        "mma.sync.aligned.m16n8k8.row.col.f32.tf32.tf32.f32 "
        "{%0,%1,%2,%3}, {%4,%5,%6,%7}, {%8,%9}, {%0,%1,%2,%3};"
        : "+f"(c[0]), "+f"(c[1]), "+f"(c[2]), "+f"(c[3])
        : "r"(a[0]), "r"(a[1]), "r"(a[2]), "r"(a[3]), "r"(b[0]), "r"(b[1]));
}

// ---------------- tf32 rounding of weights ----------------
__global__ void round_tf32_kernel(const float4* __restrict__ in, float4* __restrict__ out, int n4) {
    for (int i = blockIdx.x * blockDim.x + threadIdx.x; i < n4; i += gridDim.x * blockDim.x) {
        float4 v = in[i];
        v.x = tf32r(v.x); v.y = tf32r(v.y); v.z = tf32r(v.z); v.w = tf32r(v.w);
        out[i] = v;
    }
}

// ---------------- block reductions (256 threads) ----------------
__device__ __forceinline__ float block_sum256(float v, float* red) {
    #pragma unroll
    for (int o = 16; o > 0; o >>= 1) v += __shfl_xor_sync(0xffffffffu, v, o);
    if ((threadIdx.x & 31) == 0) red[threadIdx.x >> 5] = v;
    __syncthreads();
    float t = 0.f;
    #pragma unroll
    for (int i = 0; i < 8; i++) t += red[i];
    __syncthreads();
    return t;
}

__device__ __forceinline__ float block_max256(float v, float* red) {
    #pragma unroll
    for (int o = 16; o > 0; o >>= 1) v = fmaxf(v, __shfl_xor_sync(0xffffffffu, v, o));
    if ((threadIdx.x & 31) == 0) red[threadIdx.x >> 5] = v;
    __syncthreads();
    float t = -INFINITY;
    #pragma unroll
    for (int i = 0; i < 8; i++) t = fmaxf(t, red[i]);
    __syncthreads();
    return t;
}

// ---------------- layernorm, output rounded to tf32 ----------------
__global__ void ln_kernel(const float* __restrict__ x, float* __restrict__ y,
                          const float* __restrict__ alpha, const float* __restrict__ beta) {
    __shared__ float red[8];
    const int row = blockIdx.x;
    const float* xr = x + (size_t)row * DM;
    float*       yr = y + (size_t)row * DM;

    float v[4];
    float s = 0.f;
    #pragma unroll
    for (int i = 0; i < 4; i++) { v[i] = xr[threadIdx.x + i*256]; s += v[i]; }
    const float mean = block_sum256(s, red) * (1.f / DM);

    float d2 = 0.f;
    #pragma unroll
    for (int i = 0; i < 4; i++) { float d = v[i] - mean; d2 += d * d; }
    const float var = block_sum256(d2, red) * (1.f / (DM - 1));   // Bessel
    const float inv = alpha[0] / (sqrtf(var) + LN_EPS);
    const float b0  = beta[0];
    #pragma unroll
    for (int i = 0; i < 4; i++)
        yr[threadIdx.x + i*256] = tf32r((v[i] - mean) * inv + b0);
}

// ---------------- softmax, output rounded to tf32 ----------------
__global__ void softmax_kernel(float* __restrict__ S) {
    __shared__ float red[8];
    float* p = S + (size_t)blockIdx.x * SEQ;
    float v[4];
    float m = -INFINITY;
    #pragma unroll
    for (int i = 0; i < 4; i++) { v[i] = p[threadIdx.x + i*256]; m = fmaxf(m, v[i]); }
    m = block_max256(m, red);
    float s = 0.f;
    #pragma unroll
    for (int i = 0; i < 4; i++) { v[i] = expf(v[i] - m); s += v[i]; }
    s = block_sum256(s, red);
    const float inv = 1.f / s;
    #pragma unroll
    for (int i = 0; i < 4; i++) p[threadIdx.x + i*256] = tf32r(v[i] * inv);
}

// =====================================================================
// tf32 tensor-core GEMM: C = A[M,K] @ B[K,N] (+bias, relu, res, round)
// 128x128 tile, BK=16, 256 threads (8 warps 2x4), double-buffered cp.async
// =====================================================================
template<bool RELU, bool RES, bool ROUND>
__global__ __launch_bounds__(256, 2)
void gemm_tf32(const float* __restrict__ A, const float* __restrict__ B,
               const float* __restrict__ bias, const float* __restrict__ res,
               float* __restrict__ C, int M, int N, int K) {
    __shared__ float As[2][128][20];    // [m][k], pad 20 -> conflict-free frags
    __shared__ float Bs[2][16][136];    // [k][n], pad 136 -> conflict-free frags

    const int tid  = threadIdx.x;
    const int wid  = tid >> 5, lane = tid & 31;
    const int wm   = wid >> 2, wn = wid & 3;
    const int g    = lane >> 2, tig = lane & 3;
    const int bm   = blockIdx.y * 128, bn = blockIdx.x * 128;

    const int a_row = tid >> 2;           // 0..63 (+64)
    const int a_kc  = (tid & 3) << 2;
    const int b_row = tid >> 5;           // 0..7 (+8)
    const int b_nc  = (tid & 31) << 2;

    const float* Ag = A + (size_t)bm * K;
    const float* Bg = B + bn;

    float acc[4][4][4] = {};

    const int NIT = K >> 4;

    // prologue: stage 0
    {
        CPA16(su(&As[0][a_row][a_kc]),    Ag + (size_t)a_row * K + a_kc);
        CPA16(su(&As[0][a_row+64][a_kc]), Ag + (size_t)(a_row+64) * K + a_kc);
        CPA16(su(&Bs[0][b_row][b_nc]),    Bg + (size_t)b_row * N + b_nc);
        CPA16(su(&Bs[0][b_row+8][b_nc]),  Bg + (size_t)(b_row+8) * N + b_nc);
        CPCOMMIT();
    }

    for (int it = 0; it < NIT; it++) {
        const int cur = it & 1;
        if (it + 1 < NIT) {
            const int nxt = cur ^ 1;
            const int k0 = (it + 1) << 4;
            CPA16(su(&As[nxt][a_row][a_kc]),    Ag + (size_t)a_row * K + k0 + a_kc);
            CPA16(su(&As[nxt][a_row+64][a_kc]), Ag + (size_t)(a_row+64) * K + k0 + a_kc);
            CPA16(su(&Bs[nxt][b_row][b_nc]),    Bg + (size_t)(k0 + b_row) * N + b_nc);
            CPA16(su(&Bs[nxt][b_row+8][b_nc]),  Bg + (size_t)(k0 + b_row + 8) * N + b_nc);
            CPCOMMIT();
            CPWAIT1();
        } else {
            CPWAIT0();
        }
        __syncthreads();

        #pragma unroll
        for (int kt = 0; kt < 2; kt++) {
            const int kb = kt << 3;
            unsigned a[4][4], b[4][2];
            #pragma unroll
            for (int mt = 0; mt < 4; mt++) {
                const int rm = wm*64 + mt*16 + g;
                a[mt][0] = __float_as_uint(As[cur][rm  ][kb+tig]);
                a[mt][1] = __float_as_uint(As[cur][rm+8][kb+tig]);
                a[mt][2] = __float_as_uint(As[cur][rm  ][kb+tig+4]);
                a[mt][3] = __float_as_uint(As[cur][rm+8][kb+tig+4]);
            }
            #pragma unroll
            for (int nt = 0; nt < 4; nt++) {
                const int cn = wn*32 + nt*8 + g;
                b[nt][0] = __float_as_uint(Bs[cur][kb+tig  ][cn]);
                b[nt][1] = __float_as_uint(Bs[cur][kb+tig+4][cn]);
            }
            #pragma unroll
            for (int mt = 0; mt < 4; mt++)
                #pragma unroll
                for (int nt = 0; nt < 4; nt++)
                    mma8(acc[mt][nt], a[mt], b[nt]);
        }
        __syncthreads();
    }

    // epilogue
    #pragma unroll
    for (int mt = 0; mt < 4; mt++) {
        const int r0 = bm + wm*64 + mt*16 + g;
        #pragma unroll
        for (int nt = 0; nt < 4; nt++) {
            const int c0 = bn + wn*32 + nt*8 + 2*tig;
            const float2 bi = *(const float2*)&bias[c0];
            float v0 = acc[mt][nt][0] + bi.x;
            float v1 = acc[mt][nt][1] + bi.y;
            float v2 = acc[mt][nt][2] + bi.x;
            float v3 = acc[mt][nt][3] + bi.y;
            if (RELU) { v0 = fmaxf(v0,0.f); v1 = fmaxf(v1,0.f); v2 = fmaxf(v2,0.f); v3 = fmaxf(v3,0.f); }
            if (RES) {
                const float2 ra = *(const float2*)&res[(size_t)r0*N + c0];
                const float2 rb = *(const float2*)&res[(size_t)(r0+8)*N + c0];
                v0 += ra.x; v1 += ra.y; v2 += rb.x; v3 += rb.y;
            }
            if (ROUND) { v0 = tf32r(v0); v1 = tf32r(v1); v2 = tf32r(v2); v3 = tf32r(v3); }
            *(float2*)&C[(size_t)r0*N + c0]     = make_float2(v0, v1);
            *(float2*)&C[(size_t)(r0+8)*N + c0] = make_float2(v2, v3);
        }
    }
}

// =====================================================================
// scores: S[bh,q,k] = (Q_bh @ K_bh^T)/8, masked.  128x128 tile, Kdim=64
// =====================================================================
__global__ __launch_bounds__(256, 2)
void scores_tf32(const float* __restrict__ Q, const float* __restrict__ Km,
                 const int* __restrict__ mask, float* __restrict__ S) {
    __shared__ float As[2][128][20];    // Q rows [q][d]
    __shared__ float Ks[2][128][20];    // K rows [kseq][d]

    const int tid = threadIdx.x;
    const int wid = tid >> 5, lane = tid & 31;
    const int wm  = wid >> 2, wn = wid & 3;
    const int g   = lane >> 2, tig = lane & 3;

    const int bh = blockIdx.z, b = bh >> 4, h = bh & 15;
    const int q0 = blockIdx.y * 128, k0 = blockIdx.x * 128;

    const int a_row = tid >> 2;
    const int a_kc  = (tid & 3) << 2;

    const float* Qg = Q + ((size_t)(b*SEQ + q0)) * DM + h*DKH;
    const float* Kg = Km + ((size_t)(b*SEQ + k0)) * DM + h*DKH;

    float acc[4][4][4] = {};

    // prologue
    {
        CPA16(su(&As[0][a_row][a_kc]),    Qg + (size_t)a_row * DM + a_kc);
        CPA16(su(&As[0][a_row+64][a_kc]), Qg + (size_t)(a_row+64) * DM + a_kc);
        CPA16(su(&Ks[0][a_row][a_kc]),    Kg + (size_t)a_row * DM + a_kc);
        CPA16(su(&Ks[0][a_row+64][a_kc]), Kg + (size_t)(a_row+64) * DM + a_kc);
        CPCOMMIT();
    }

    for (int it = 0; it < 4; it++) {        // 64 / 16
        const int cur = it & 1;
        if (it + 1 < 4) {
            const int nxt = cur ^ 1;
            const int kd = (it + 1) << 4;
            CPA16(su(&As[nxt][a_row][a_kc]),    Qg + (size_t)a_row * DM + kd + a_kc);
            CPA16(su(&As[nxt][a_row+64][a_kc]), Qg + (size_t)(a_row+64) * DM + kd + a_kc);
            CPA16(su(&Ks[nxt][a_row][a_kc]),    Kg + (size_t)a_row * DM + kd + a_kc);
            CPA16(su(&Ks[nxt][a_row+64][a_kc]), Kg + (size_t)(a_row+64) * DM + kd + a_kc);
            CPCOMMIT();
            CPWAIT1();
        } else {
            CPWAIT0();
        }
        __syncthreads();

        #pragma unroll
        for (int kt = 0; kt < 2; kt++) {
            const int kb = kt << 3;
            unsigned a[4][4], bfr[4][2];
            #pragma unroll
            for (int mt = 0; mt < 4; mt++) {
                const int rm = wm*64 + mt*16 + g;
                a[mt][0] = __float_as_uint(As[cur][rm  ][kb+tig]);
                a[mt][1] = __float_as_uint(As[cur][rm+8][kb+tig]);
                a[mt][2] = __float_as_uint(As[cur][rm  ][kb+tig+4]);
                a[mt][3] = __float_as_uint(As[cur][rm+8][kb+tig+4]);
            }
            #pragma unroll
            for (int nt = 0; nt < 4; nt++) {
                const int cn = wn*32 + nt*8 + g;
                bfr[nt][0] = __float_as_uint(Ks[cur][cn][kb+tig]);
                bfr[nt][1] = __float_as_uint(Ks[cur][cn][kb+tig+4]);
            }
            #pragma unroll
            for (int mt = 0; mt < 4; mt++)
                #pragma unroll
                for (int nt = 0; nt < 4; nt++)
                    mma8(acc[mt][nt], a[mt], bfr[nt]);
        }
        __syncthreads();
    }

    float* Sp = S + (size_t)bh * SEQ * SEQ;
    #pragma unroll
    for (int mt = 0; mt < 4; mt++) {
        const int r0 = q0 + wm*64 + mt*16 + g;
        #pragma unroll
        for (int nt = 0; nt < 4; nt++) {
            const int c0 = k0 + wn*32 + nt*8 + 2*tig;
            const int2 mk = *(const int2*)&mask[b*SEQ + c0];
            float v0 = acc[mt][nt][0] * 0.125f;
            float v1 = acc[mt][nt][1] * 0.125f;
            float v2 = acc[mt][nt][2] * 0.125f;
            float v3 = acc[mt][nt][3] * 0.125f;
            if (mk.x == 0) { v0 = NEGINF; v2 = NEGINF; }
            if (mk.y == 0) { v1 = NEGINF; v3 = NEGINF; }
            *(float2*)&Sp[(size_t)r0*SEQ + c0]     = make_float2(v0, v1);
            *(float2*)&Sp[(size_t)(r0+8)*SEQ + c0] = make_float2(v2, v3);
        }
    }
}

// =====================================================================
// attnv: O[b, m, h*64+d] = sum_k P[bh,m,k] * V[b,k,h*64+d]
// 128x64 tile, BK=16, 256 threads (8 warps 4x2), Kdim=1024
// =====================================================================
__global__ __launch_bounds__(256, 2)
void attnv_tf32(const float* __restrict__ P, const float* __restrict__ V,
                float* __restrict__ O) {
    __shared__ float As[2][128][20];    // P rows
    __shared__ float Bs[2][16][72];     // V [k][d], pad 72 -> conflict-free

    const int tid = threadIdx.x;
    const int wid = tid >> 5, lane = tid & 31;
    const int wm  = wid >> 1, wn = wid & 1;         // 4 x 2 warps
    const int g   = lane >> 2, tig = lane & 3;

    const int bh = blockIdx.y, b = bh >> 4, h = bh & 15;
    const int m0 = blockIdx.x * 128;

    const int a_row = tid >> 2;
    const int a_kc  = (tid & 3) << 2;
    const int b_row = tid >> 4;          // 0..15
    const int b_nc  = (tid & 15) << 2;

    const float* Pg = P + ((size_t)bh * SEQ + m0) * SEQ;
    const float* Vg = V + (size_t)(b*SEQ) * DM + h*DKH;

    float acc[2][4][4] = {};

    // prologue
    {
        CPA16(su(&As[0][a_row][a_kc]),    Pg + (size_t)a_row * SEQ + a_kc);
        CPA16(su(&As[0][a_row+64][a_kc]), Pg + (size_t)(a_row+64) * SEQ + a_kc);
        CPA16(su(&Bs[0][b_row][b_nc]),    Vg + (size_t)b_row * DM + b_nc);
        CPCOMMIT();
    }

    for (int it = 0; it < SEQ/16; it++) {
        const int cur = it & 1;
        if (it + 1 < SEQ/16) {
            const int nxt = cur ^ 1;
            const int k0 = (it + 1) << 4;
            CPA16(su(&As[nxt][a_row][a_kc]),    Pg + (size_t)a_row * SEQ + k0 + a_kc);
            CPA16(su(&As[nxt][a_row+64][a_kc]), Pg + (size_t)(a_row+64) * SEQ + k0 + a_kc);
            CPA16(su(&Bs[nxt][b_row][b_nc]),    Vg + (size_t)(k0 + b_row) * DM + b_nc);
            CPCOMMIT();
            CPWAIT1();
        } else {
            CPWAIT0();
        }
        __syncthreads();

        #pragma unroll
        for (int kt = 0; kt < 2; kt++) {
            const int kb = kt << 3;
            unsigned a[2][4], bfr[4][2];
            #pragma unroll
            for (int mt = 0; mt < 2; mt++) {
                const int rm = wm*32 + mt*16 + g;
                a[mt][0] = __float_as_uint(As[cur][rm  ][kb+tig]);
                a[mt][1] = __float_as_uint(As[cur][rm+8][kb+tig]);
                a[mt][2] = __float_as_uint(As[cur][rm  ][kb+tig+4]);
                a[mt][3] = __float_as_uint(As[cur][rm+8][kb+tig+4]);
            }
            #pragma unroll
            for (int nt = 0; nt < 4; nt++) {
                const int cn = wn*32 + nt*8 + g;
                bfr[nt][0] = __float_as_uint(Bs[cur][kb+tig  ][cn]);
                bfr[nt][1] = __float_as_uint(Bs[cur][kb+tig+4][cn]);
            }
            #pragma unroll
            for (int mt = 0; mt < 2; mt++)
                #pragma unroll
                for (int nt = 0; nt < 4; nt++)
                    mma8(acc[mt][nt], a[mt], bfr[nt]);
        }
        __syncthreads();
    }

    #pragma unroll
    for (int mt = 0; mt < 2; mt++) {
        const int r0 = m0 + wm*32 + mt*16 + g;
        #pragma unroll
        for (int nt = 0; nt < 4; nt++) {
            const int c0 = wn*32 + nt*8 + 2*tig;
            float v0 = tf32r(acc[mt][nt][0]);
            float v1 = tf32r(acc[mt][nt][1]);
            float v2 = tf32r(acc[mt][nt][2]);
            float v3 = tf32r(acc[mt][nt][3]);
            *(float2*)&O[(size_t)(b*SEQ + r0)*DM + h*DKH + c0]     = make_float2(v0, v1);
            *(float2*)&O[(size_t)(b*SEQ + r0 + 8)*DM + h*DKH + c0] = make_float2(v2, v3);
        }
    }
}

// ---------------- launch ----------------
extern "C" void kernel_launch(void* const* d_in, const int* in_sizes, int n_in,
                              void* d_out, int out_size) {
    const float* x   = (const float*)d_in[0];
    const int*   mask= (const int*)  d_in[1];
    const float* Wq  = (const float*)d_in[2];
    const float* bq  = (const float*)d_in[3];
    const float* Wk  = (const float*)d_in[4];
    const float* bk  = (const float*)d_in[5];
    const float* Wv  = (const float*)d_in[6];
    const float* bv  = (const float*)d_in[7];
    const float* Wo  = (const float*)d_in[8];
    const float* bo  = (const float*)d_in[9];
    const float* W1  = (const float*)d_in[10];
    const float* b1  = (const float*)d_in[11];
    const float* W2  = (const float*)d_in[12];
    const float* b2  = (const float*)d_in[13];
    const float* a1  = (const float*)d_in[14];
    const float* be1 = (const float*)d_in[15];
    const float* a2  = (const float*)d_in[16];
    const float* be2 = (const float*)d_in[17];
    float* out = (float*)d_out;

    float *xn, *q, *k, *v, *sc, *at, *x1, *ff;
    float *wq, *wk, *wv, *wo, *w1, *w2;
    cudaGetSymbolAddress((void**)&xn, g_xn);
    cudaGetSymbolAddress((void**)&q,  g_q);
    cudaGetSymbolAddress((void**)&k,  g_k);
    cudaGetSymbolAddress((void**)&v,  g_v);
    cudaGetSymbolAddress((void**)&sc, g_sc);
    cudaGetSymbolAddress((void**)&at, g_at);
    cudaGetSymbolAddress((void**)&x1, g_x1);
    cudaGetSymbolAddress((void**)&ff, g_ff);
    cudaGetSymbolAddress((void**)&wq, g_wq);
    cudaGetSymbolAddress((void**)&wk, g_wk);
    cudaGetSymbolAddress((void**)&wv, g_wv);
    cudaGetSymbolAddress((void**)&wo, g_wo);
    cudaGetSymbolAddress((void**)&w1, g_w1);
    cudaGetSymbolAddress((void**)&w2, g_w2);

    // 0) round weights to tf32 once
    round_tf32_kernel<<<512, 256>>>((const float4*)Wq, (float4*)wq, DM*DM/4);
    round_tf32_kernel<<<512, 256>>>((const float4*)Wk, (float4*)wk, DM*DM/4);
    round_tf32_kernel<<<512, 256>>>((const float4*)Wv, (float4*)wv, DM*DM/4);
    round_tf32_kernel<<<512, 256>>>((const float4*)Wo, (float4*)wo, DM*DM/4);
    round_tf32_kernel<<<1024, 256>>>((const float4*)W1, (float4*)w1, DM*DFF/4);
    round_tf32_kernel<<<1024, 256>>>((const float4*)W2, (float4*)w2, DFF*DM/4);

    // 1) LN1 (rounded output)
    ln_kernel<<<ROWS, 256>>>(x, xn, a1, be1);
    // 2-4) Q,K,V projections (rounded outputs)
    gemm_tf32<false,false,true><<<dim3(DM/128, ROWS/128), 256>>>(xn, wq, bq, nullptr, q, ROWS, DM, DM);
    gemm_tf32<false,false,true><<<dim3(DM/128, ROWS/128), 256>>>(xn, wk, bk, nullptr, k, ROWS, DM, DM);
    gemm_tf32<false,false,true><<<dim3(DM/128, ROWS/128), 256>>>(xn, wv, bv, nullptr, v, ROWS, DM, DM);
    // 5) scores
    scores_tf32<<<dim3(SEQ/128, SEQ/128, BATCH*NH), 256>>>(q, k, mask, sc);
    // 6) softmax (rounded output)
    softmax_kernel<<<BATCH*NH*SEQ, 256>>>(sc);
    // 7) attn @ V (rounded output)
    attnv_tf32<<<dim3(SEQ/128, BATCH*NH), 256>>>(sc, v, at);
    // 8) output projection + residual(x)
    gemm_tf32<false,true,false><<<dim3(DM/128, ROWS/128), 256>>>(at, wo, bo, x, x1, ROWS, DM, DM);
    // 9) LN2 (rounded output)
    ln_kernel<<<ROWS, 256>>>(x1, xn, a2, be2);
    // 10) FFN up + relu (rounded output)
    gemm_tf32<true,false,true><<<dim3(DFF/128, ROWS/128), 256>>>(xn, w1, b1, nullptr, ff, ROWS, DFF, DM);
    // 11) FFN down + residual(x1) -> out
    gemm_tf32<false,true,false><<<dim3(DM/128, ROWS/128), 256>>>(ff, w2, b2, x1, out, ROWS, DM, DFF);
}

// round 4
// speedup vs baseline: 3.6547x; 1.0695x over previous
#include <cuda_runtime.h>
#include <math.h>
#include <stdint.h>

#define SEQ   1024
#define BATCH 4
#define DM    1024
#define NH    16
#define DKH   64
#define DFF   4096
#define ROWS  (BATCH*SEQ)       // 4096
#define QKVS  (3*DM)            // 3072 fused qkv row stride
#define LN_EPS 1e-6f
#define NEGINF -1e9f

// ---------------- scratch (device globals; no allocation) ----------------
__device__ float g_xn [ROWS*DM];
__device__ float g_qkv[(size_t)ROWS*QKVS];            // 48 MB
__device__ float g_sc [(size_t)BATCH*NH*SEQ*SEQ];     // 256 MB
__device__ float g_at [ROWS*DM];
__device__ float g_x1 [ROWS*DM];
__device__ float g_ff [(size_t)ROWS*DFF];             // 64 MB
__device__ float g_wqkv[DM*QKVS];                     // 12 MB
__device__ float g_bqkv[QKVS];
__device__ float g_wo[DM*DM];
__device__ float g_w1[DM*DFF];
__device__ float g_w2[DFF*DM];

// ---------------- helpers ----------------
__device__ __forceinline__ float tf32r(float x) {
    unsigned u;
    asm("cvt.rna.tf32.f32 %0, %1;" : "=r"(u) : "f"(x));
    return __uint_as_float(u);
}
__device__ __forceinline__ unsigned su(const void* p) {
    return (unsigned)__cvta_generic_to_shared(p);
}
#define CPA16(dst, src) asm volatile("cp.async.cg.shared.global [%0], [%1], 16;" :: "r"(dst), "l"(src))
#define CPCOMMIT()      asm volatile("cp.async.commit_group;")
#define CPWAIT1()       asm volatile("cp.async.wait_group 1;")
#define CPWAIT0()       asm volatile("cp.async.wait_group 0;")

__device__ __forceinline__ void mma8(float* c, const unsigned* a, const unsigned* b) {
    asm volatile(
        "mma.sync.aligned.m16n8k8.row.col.f32.tf32.tf32.f32 "
        "{%0,%1,%2,%3}, {%4,%5,%6,%7}, {%8,%9}, {%0,%1,%2,%3};"
        : "+f"(c[0]), "+f"(c[1]), "+f"(c[2]), "+f"(c[3])
        : "r"(a[0]), "r"(a[1]), "r"(a[2]), "r"(a[3]), "r"(b[0]), "r"(b[1]));
}

// ---------------- tf32 rounding (optionally into strided/offset layout) ---
__global__ void round_cat_kernel(const float4* __restrict__ in, float4* __restrict__ out,
                                 int n4, int rowLen4, int stride4, int off4) {
    for (int i = blockIdx.x * blockDim.x + threadIdx.x; i < n4; i += gridDim.x * blockDim.x) {
        float4 v = in[i];
        v.x = tf32r(v.x); v.y = tf32r(v.y); v.z = tf32r(v.z); v.w = tf32r(v.w);
        int r = i / rowLen4, c = i - r * rowLen4;
        out[(size_t)r * stride4 + off4 + c] = v;
    }
}

__global__ void bias_cat_kernel(const float* __restrict__ b0, const float* __restrict__ b1,
                                const float* __restrict__ b2, float* __restrict__ out) {
    int i = blockIdx.x * blockDim.x + threadIdx.x;
    if (i < DM) out[i] = b0[i];
    else if (i < 2*DM) out[i] = b1[i - DM];
    else if (i < 3*DM) out[i] = b2[i - 2*DM];
}

// ---------------- block reductions (256 threads) ----------------
__device__ __forceinline__ float block_sum256(float v, float* red) {
    #pragma unroll
    for (int o = 16; o > 0; o >>= 1) v += __shfl_xor_sync(0xffffffffu, v, o);
    if ((threadIdx.x & 31) == 0) red[threadIdx.x >> 5] = v;
    __syncthreads();
    float t = 0.f;
    #pragma unroll
    for (int i = 0; i < 8; i++) t += red[i];
    __syncthreads();
    return t;
}
__device__ __forceinline__ float block_max256(float v, float* red) {
    #pragma unroll
    for (int o = 16; o > 0; o >>= 1) v = fmaxf(v, __shfl_xor_sync(0xffffffffu, v, o));
    if ((threadIdx.x & 31) == 0) red[threadIdx.x >> 5] = v;
    __syncthreads();
    float t = -INFINITY;
    #pragma unroll
    for (int i = 0; i < 8; i++) t = fmaxf(t, red[i]);
    __syncthreads();
    return t;
}

// ---------------- layernorm (tf32-rounded output) ----------------
__global__ void ln_kernel(const float* __restrict__ x, float* __restrict__ y,
                          const float* __restrict__ alpha, const float* __restrict__ beta) {
    __shared__ float red[8];
    const int row = blockIdx.x;
    const float* xr = x + (size_t)row * DM;
    float*       yr = y + (size_t)row * DM;

    float v[4];
    float s = 0.f;
    #pragma unroll
    for (int i = 0; i < 4; i++) { v[i] = xr[threadIdx.x + i*256]; s += v[i]; }
    const float mean = block_sum256(s, red) * (1.f / DM);

    float d2 = 0.f;
    #pragma unroll
    for (int i = 0; i < 4; i++) { float d = v[i] - mean; d2 += d * d; }
    const float var = block_sum256(d2, red) * (1.f / (DM - 1));
    const float inv = alpha[0] / (sqrtf(var) + LN_EPS);
    const float b0  = beta[0];
    #pragma unroll
    for (int i = 0; i < 4; i++)
        yr[threadIdx.x + i*256] = tf32r((v[i] - mean) * inv + b0);
}

// ---------------- softmax (tf32-rounded output) ----------------
__global__ void softmax_kernel(float* __restrict__ S) {
    __shared__ float red[8];
    float* p = S + (size_t)blockIdx.x * SEQ;
    float v[4];
    float m = -INFINITY;
    #pragma unroll
    for (int i = 0; i < 4; i++) { v[i] = p[threadIdx.x + i*256]; m = fmaxf(m, v[i]); }
    m = block_max256(m, red);
    float s = 0.f;
    #pragma unroll
    for (int i = 0; i < 4; i++) { v[i] = expf(v[i] - m); s += v[i]; }
    s = block_sum256(s, red);
    const float inv = 1.f / s;
    #pragma unroll
    for (int i = 0; i < 4; i++) p[threadIdx.x + i*256] = tf32r(v[i] * inv);
}

// =====================================================================
// tf32 tensor-core GEMM: C = A[M,K] @ B[K,N] (+bias, relu, res, round)
// 128x128 tile, BK=16, 128 threads (4 warps 2x2, warp-tile 64x64)
// =====================================================================
template<bool RELU, bool RES, bool ROUND>
__global__ __launch_bounds__(128, 2)
void gemm_tf32(const float* __restrict__ A, const float* __restrict__ B,
               const float* __restrict__ bias, const float* __restrict__ res,
               float* __restrict__ C, int M, int N, int K) {
    __shared__ float As[2][128][20];    // [m][k]
    __shared__ float Bs[2][16][136];    // [k][n]

    const int tid  = threadIdx.x;
    const int wid  = tid >> 5, lane = tid & 31;
    const int wm   = wid >> 1, wn = wid & 1;
    const int g    = lane >> 2, tig = lane & 3;
    const int bm   = blockIdx.y * 128, bn = blockIdx.x * 128;

    const int a_row = tid >> 2;           // 0..31 (+32,+64,+96)
    const int a_kc  = (tid & 3) << 2;
    const int b_row = tid >> 5;           // 0..3 (+4,+8,+12)
    const int b_nc  = (tid & 31) << 2;

    const float* Ag = A + (size_t)bm * K;
    const float* Bg = B + bn;

    float acc[4][8][4] = {};
    const int NIT = K >> 4;

    // prologue: stage 0
    #pragma unroll
    for (int j = 0; j < 4; j++) {
        CPA16(su(&As[0][a_row + 32*j][a_kc]), Ag + (size_t)(a_row + 32*j) * K + a_kc);
        CPA16(su(&Bs[0][b_row + 4*j][b_nc]),  Bg + (size_t)(b_row + 4*j) * N + b_nc);
    }
    CPCOMMIT();

    for (int it = 0; it < NIT; it++) {
        const int cur = it & 1;
        if (it + 1 < NIT) {
            const int nxt = cur ^ 1;
            const int k0 = (it + 1) << 4;
            #pragma unroll
            for (int j = 0; j < 4; j++) {
                CPA16(su(&As[nxt][a_row + 32*j][a_kc]), Ag + (size_t)(a_row + 32*j) * K + k0 + a_kc);
                CPA16(su(&Bs[nxt][b_row + 4*j][b_nc]),  Bg + (size_t)(k0 + b_row + 4*j) * N + b_nc);
            }
            CPCOMMIT();
            CPWAIT1();
        } else {
            CPWAIT0();
        }
        __syncthreads();

        #pragma unroll
        for (int kt = 0; kt < 2; kt++) {
            const int kb = kt << 3;
            unsigned a[4][4], b[8][2];
            #pragma unroll
            for (int mt = 0; mt < 4; mt++) {
                const int rm = wm*64 + mt*16 + g;
                a[mt][0] = __float_as_uint(As[cur][rm  ][kb+tig]);
                a[mt][1] = __float_as_uint(As[cur][rm+8][kb+tig]);
                a[mt][2] = __float_as_uint(As[cur][rm  ][kb+tig+4]);
                a[mt][3] = __float_as_uint(As[cur][rm+8][kb+tig+4]);
            }
            #pragma unroll
            for (int nt = 0; nt < 8; nt++) {
                const int cn = wn*64 + nt*8 + g;
                b[nt][0] = __float_as_uint(Bs[cur][kb+tig  ][cn]);
                b[nt][1] = __float_as_uint(Bs[cur][kb+tig+4][cn]);
            }
            #pragma unroll
            for (int mt = 0; mt < 4; mt++)
                #pragma unroll
                for (int nt = 0; nt < 8; nt++)
                    mma8(acc[mt][nt], a[mt], b[nt]);
        }
        __syncthreads();
    }

    // epilogue
    #pragma unroll
    for (int mt = 0; mt < 4; mt++) {
        const int r0 = bm + wm*64 + mt*16 + g;
        #pragma unroll
        for (int nt = 0; nt < 8; nt++) {
            const int c0 = bn + wn*64 + nt*8 + 2*tig;
            const float2 bi = *(const float2*)&bias[c0];
            float v0 = acc[mt][nt][0] + bi.x;
            float v1 = acc[mt][nt][1] + bi.y;
            float v2 = acc[mt][nt][2] + bi.x;
            float v3 = acc[mt][nt][3] + bi.y;
            if (RELU) { v0 = fmaxf(v0,0.f); v1 = fmaxf(v1,0.f); v2 = fmaxf(v2,0.f); v3 = fmaxf(v3,0.f); }
            if (RES) {
                const float2 ra = *(const float2*)&res[(size_t)r0*N + c0];
                const float2 rb = *(const float2*)&res[(size_t)(r0+8)*N + c0];
                v0 += ra.x; v1 += ra.y; v2 += rb.x; v3 += rb.y;
            }
            if (ROUND) { v0 = tf32r(v0); v1 = tf32r(v1); v2 = tf32r(v2); v3 = tf32r(v3); }
            *(float2*)&C[(size_t)r0*N + c0]     = make_float2(v0, v1);
            *(float2*)&C[(size_t)(r0+8)*N + c0] = make_float2(v2, v3);
        }
    }
}

// =====================================================================
// scores: S[bh,q,k] = (Q_bh @ K_bh^T)/8, masked.  128x128 tile, Kdim=64
// Q/K read from fused qkv buffer (row stride QKVS)
// =====================================================================
__global__ __launch_bounds__(256, 2)
void scores_tf32(const float* __restrict__ QKV, const int* __restrict__ mask,
                 float* __restrict__ S) {
    __shared__ float As[2][128][20];
    __shared__ float Ks[2][128][20];

    const int tid = threadIdx.x;
    const int wid = tid >> 5, lane = tid & 31;
    const int wm  = wid >> 2, wn = wid & 3;
    const int g   = lane >> 2, tig = lane & 3;

    const int bh = blockIdx.z, b = bh >> 4, h = bh & 15;
    const int q0 = blockIdx.y * 128, k0 = blockIdx.x * 128;

    const int a_row = tid >> 2;
    const int a_kc  = (tid & 3) << 2;

    const float* Qg = QKV + ((size_t)(b*SEQ + q0)) * QKVS + h*DKH;
    const float* Kg = QKV + ((size_t)(b*SEQ + k0)) * QKVS + DM + h*DKH;

    float acc[4][4][4] = {};

    {
        CPA16(su(&As[0][a_row][a_kc]),    Qg + (size_t)a_row * QKVS + a_kc);
        CPA16(su(&As[0][a_row+64][a_kc]), Qg + (size_t)(a_row+64) * QKVS + a_kc);
        CPA16(su(&Ks[0][a_row][a_kc]),    Kg + (size_t)a_row * QKVS + a_kc);
        CPA16(su(&Ks[0][a_row+64][a_kc]), Kg + (size_t)(a_row+64) * QKVS + a_kc);
        CPCOMMIT();
    }

    for (int it = 0; it < 4; it++) {
        const int cur = it & 1;
        if (it + 1 < 4) {
            const int nxt = cur ^ 1;
            const int kd = (it + 1) << 4;
            CPA16(su(&As[nxt][a_row][a_kc]),    Qg + (size_t)a_row * QKVS + kd + a_kc);
            CPA16(su(&As[nxt][a_row+64][a_kc]), Qg + (size_t)(a_row+64) * QKVS + kd + a_kc);
            CPA16(su(&Ks[nxt][a_row][a_kc]),    Kg + (size_t)a_row * QKVS + kd + a_kc);
            CPA16(su(&Ks[nxt][a_row+64][a_kc]), Kg + (size_t)(a_row+64) * QKVS + kd + a_kc);
            CPCOMMIT();
            CPWAIT1();
        } else {
            CPWAIT0();
        }
        __syncthreads();

        #pragma unroll
        for (int kt = 0; kt < 2; kt++) {
            const int kb = kt << 3;
            unsigned a[4][4], bfr[4][2];
            #pragma unroll
            for (int mt = 0; mt < 4; mt++) {
                const int rm = wm*64 + mt*16 + g;
                a[mt][0] = __float_as_uint(As[cur][rm  ][kb+tig]);
                a[mt][1] = __float_as_uint(As[cur][rm+8][kb+tig]);
                a[mt][2] = __float_as_uint(As[cur][rm  ][kb+tig+4]);
                a[mt][3] = __float_as_uint(As[cur][rm+8][kb+tig+4]);
            }
            #pragma unroll
            for (int nt = 0; nt < 4; nt++) {
                const int cn = wn*32 + nt*8 + g;
                bfr[nt][0] = __float_as_uint(Ks[cur][cn][kb+tig]);
                bfr[nt][1] = __float_as_uint(Ks[cur][cn][kb+tig+4]);
            }
            #pragma unroll
            for (int mt = 0; mt < 4; mt++)
                #pragma unroll
                for (int nt = 0; nt < 4; nt++)
                    mma8(acc[mt][nt], a[mt], bfr[nt]);
        }
        __syncthreads();
    }

    float* Sp = S + (size_t)bh * SEQ * SEQ;
    #pragma unroll
    for (int mt = 0; mt < 4; mt++) {
        const int r0 = q0 + wm*64 + mt*16 + g;
        #pragma unroll
        for (int nt = 0; nt < 4; nt++) {
            const int c0 = k0 + wn*32 + nt*8 + 2*tig;
            const int2 mk = *(const int2*)&mask[b*SEQ + c0];
            float v0 = acc[mt][nt][0] * 0.125f;
            float v1 = acc[mt][nt][1] * 0.125f;
            float v2 = acc[mt][nt][2] * 0.125f;
            float v3 = acc[mt][nt][3] * 0.125f;
            if (mk.x == 0) { v0 = NEGINF; v2 = NEGINF; }
            if (mk.y == 0) { v1 = NEGINF; v3 = NEGINF; }
            *(float2*)&Sp[(size_t)r0*SEQ + c0]     = make_float2(v0, v1);
            *(float2*)&Sp[(size_t)(r0+8)*SEQ + c0] = make_float2(v2, v3);
        }
    }
}

// =====================================================================
// attnv: O[b, m, h*64+d] = sum_k P[bh,m,k] * V_qkv[b,k][2048 + h*64+d]
// =====================================================================
__global__ __launch_bounds__(256, 2)
void attnv_tf32(const float* __restrict__ P, const float* __restrict__ QKV,
                float* __restrict__ O) {
    __shared__ float As[2][128][20];
    __shared__ float Bs[2][16][72];

    const int tid = threadIdx.x;
    const int wid = tid >> 5, lane = tid & 31;
    const int wm  = wid >> 1, wn = wid & 1;
    const int g   = lane >> 2, tig = lane & 3;

    const int bh = blockIdx.y, b = bh >> 4, h = bh & 15;
    const int m0 = blockIdx.x * 128;

    const int a_row = tid >> 2;
    const int a_kc  = (tid & 3) << 2;
    const int b_row = tid >> 4;
    const int b_nc  = (tid & 15) << 2;

    const float* Pg = P + ((size_t)bh * SEQ + m0) * SEQ;
    const float* Vg = QKV + (size_t)(b*SEQ) * QKVS + 2*DM + h*DKH;

    float acc[2][4][4] = {};

    {
        CPA16(su(&As[0][a_row][a_kc]),    Pg + (size_t)a_row * SEQ + a_kc);
        CPA16(su(&As[0][a_row+64][a_kc]), Pg + (size_t)(a_row+64) * SEQ + a_kc);
        CPA16(su(&Bs[0][b_row][b_nc]),    Vg + (size_t)b_row * QKVS + b_nc);
        CPCOMMIT();
    }

    for (int it = 0; it < SEQ/16; it++) {
        const int cur = it & 1;
        if (it + 1 < SEQ/16) {
            const int nxt = cur ^ 1;
            const int k0 = (it + 1) << 4;
            CPA16(su(&As[nxt][a_row][a_kc]),    Pg + (size_t)a_row * SEQ + k0 + a_kc);
            CPA16(su(&As[nxt][a_row+64][a_kc]), Pg + (size_t)(a_row+64) * SEQ + k0 + a_kc);
            CPA16(su(&Bs[nxt][b_row][b_nc]),    Vg + (size_t)(k0 + b_row) * QKVS + b_nc);
            CPCOMMIT();
            CPWAIT1();
        } else {
            CPWAIT0();
        }
        __syncthreads();

        #pragma unroll
        for (int kt = 0; kt < 2; kt++) {
            const int kb = kt << 3;
            unsigned a[2][4], bfr[4][2];
            #pragma unroll
            for (int mt = 0; mt < 2; mt++) {
                const int rm = wm*32 + mt*16 + g;
                a[mt][0] = __float_as_uint(As[cur][rm  ][kb+tig]);
                a[mt][1] = __float_as_uint(As[cur][rm+8][kb+tig]);
                a[mt][2] = __float_as_uint(As[cur][rm  ][kb+tig+4]);
                a[mt][3] = __float_as_uint(As[cur][rm+8][kb+tig+4]);
            }
            #pragma unroll
            for (int nt = 0; nt < 4; nt++) {
                const int cn = wn*32 + nt*8 + g;
                bfr[nt][0] = __float_as_uint(Bs[cur][kb+tig  ][cn]);
                bfr[nt][1] = __float_as_uint(Bs[cur][kb+tig+4][cn]);
            }
            #pragma unroll
            for (int mt = 0; mt < 2; mt++)
                #pragma unroll
                for (int nt = 0; nt < 4; nt++)
                    mma8(acc[mt][nt], a[mt], bfr[nt]);
        }
        __syncthreads();
    }

    #pragma unroll
    for (int mt = 0; mt < 2; mt++) {
        const int r0 = m0 + wm*32 + mt*16 + g;
        #pragma unroll
        for (int nt = 0; nt < 4; nt++) {
            const int c0 = wn*32 + nt*8 + 2*tig;
            float v0 = tf32r(acc[mt][nt][0]);
            float v1 = tf32r(acc[mt][nt][1]);
            float v2 = tf32r(acc[mt][nt][2]);
            float v3 = tf32r(acc[mt][nt][3]);
            *(float2*)&O[(size_t)(b*SEQ + r0)*DM + h*DKH + c0]     = make_float2(v0, v1);
            *(float2*)&O[(size_t)(b*SEQ + r0 + 8)*DM + h*DKH + c0] = make_float2(v2, v3);
        }
    }
}

// ---------------- launch ----------------
extern "C" void kernel_launch(void* const* d_in, const int* in_sizes, int n_in,
                              void* d_out, int out_size) {
    const float* x   = (const float*)d_in[0];
    const int*   mask= (const int*)  d_in[1];
    const float* Wq  = (const float*)d_in[2];
    const float* bq  = (const float*)d_in[3];
    const float* Wk  = (const float*)d_in[4];
    const float* bk  = (const float*)d_in[5];
    const float* Wv  = (const float*)d_in[6];
    const float* bv  = (const float*)d_in[7];
    const float* Wo  = (const float*)d_in[8];
    const float* bo  = (const float*)d_in[9];
    const float* W1  = (const float*)d_in[10];
    const float* b1  = (const float*)d_in[11];
    const float* W2  = (const float*)d_in[12];
    const float* b2  = (const float*)d_in[13];
    const float* a1  = (const float*)d_in[14];
    const float* be1 = (const float*)d_in[15];
    const float* a2  = (const float*)d_in[16];
    const float* be2 = (const float*)d_in[17];
    float* out = (float*)d_out;

    float *xn, *qkv, *sc, *at, *x1, *ff, *wqkv, *bqkv, *wo, *w1, *w2;
    cudaGetSymbolAddress((void**)&xn,   g_xn);
    cudaGetSymbolAddress((void**)&qkv,  g_qkv);
    cudaGetSymbolAddress((void**)&sc,   g_sc);
    cudaGetSymbolAddress((void**)&at,   g_at);
    cudaGetSymbolAddress((void**)&x1,   g_x1);
    cudaGetSymbolAddress((void**)&ff,   g_ff);
    cudaGetSymbolAddress((void**)&wqkv, g_wqkv);
    cudaGetSymbolAddress((void**)&bqkv, g_bqkv);
    cudaGetSymbolAddress((void**)&wo,   g_wo);
    cudaGetSymbolAddress((void**)&w1,   g_w1);
    cudaGetSymbolAddress((void**)&w2,   g_w2);

    const int R4 = DM/4;   // 256 float4 per weight row

    // 0) round weights to tf32 (QKV concatenated into one [DM, 3072] buffer)
    round_cat_kernel<<<512, 256>>>((const float4*)Wq, (float4*)wqkv, DM*DM/4, R4, 3*R4, 0);
    round_cat_kernel<<<512, 256>>>((const float4*)Wk, (float4*)wqkv, DM*DM/4, R4, 3*R4, R4);
    round_cat_kernel<<<512, 256>>>((const float4*)Wv, (float4*)wqkv, DM*DM/4, R4, 3*R4, 2*R4);
    round_cat_kernel<<<512, 256>>>((const float4*)Wo, (float4*)wo,   DM*DM/4, R4, R4, 0);
    round_cat_kernel<<<1024, 256>>>((const float4*)W1, (float4*)w1, DM*DFF/4, DFF/4, DFF/4, 0);
    round_cat_kernel<<<1024, 256>>>((const float4*)W2, (float4*)w2, DFF*DM/4, R4, R4, 0);
    bias_cat_kernel<<<QKVS/256, 256>>>(bq, bk, bv, bqkv);

    // 1) LN1
    ln_kernel<<<ROWS, 256>>>(x, xn, a1, be1);
    // 2) fused QKV projection: [4096,1024] @ [1024,3072]
    gemm_tf32<false,false,true><<<dim3(QKVS/128, ROWS/128), 128>>>(xn, wqkv, bqkv, nullptr, qkv, ROWS, QKVS, DM);
    // 3) scores
    scores_tf32<<<dim3(SEQ/128, SEQ/128, BATCH*NH), 256>>>(qkv, mask, sc);
    // 4) softmax
    softmax_kernel<<<BATCH*NH*SEQ, 256>>>(sc);
    // 5) attn @ V
    attnv_tf32<<<dim3(SEQ/128, BATCH*NH), 256>>>(sc, qkv, at);
    // 6) output projection + residual(x)
    gemm_tf32<false,true,false><<<dim3(DM/128, ROWS/128), 128>>>(at, wo, bo, x, x1, ROWS, DM, DM);
    // 7) LN2
    ln_kernel<<<ROWS, 256>>>(x1, xn, a2, be2);
    // 8) FFN up + relu
    gemm_tf32<true,false,true><<<dim3(DFF/128, ROWS/128), 128>>>(xn, w1, b1, nullptr, ff, ROWS, DFF, DM);
    // 9) FFN down + residual(x1) -> out
    gemm_tf32<false,true,false><<<dim3(DM/128, ROWS/128), 128>>>(ff, w2, b2, x1, out, ROWS, DM, DFF);
}